// round 16
// baseline (speedup 1.0000x reference)
#include <cuda_runtime.h>
#include <cuda_fp16.h>
#include <cstdint>
#include <math.h>

#define HEAD 64
#define NEMB 1024
#define BATCH 8
#define SEQ   2048
#define MTOT  (BATCH*SEQ)   // 16384
#define NTB   (SEQ/64)      // 32 t-blocks per batch

// scratch: projected k,q,v fp16 (6.3 MB) + fp16 weights
// NOTE: k is pre-scaled by log2e/32, v by ln2 (folded softplus constants).
__device__ __half g_kqv[3][MTOT][HEAD];
__device__ __half g_Wh[3][HEAD][NEMB];   // Wh[p][n][k] = half(W[p][k][n])

// D += A*B : m16n8k16 fp16 inputs, fp32 accum
__device__ __forceinline__ void mma16(float c[4], const uint32_t a[4], uint32_t b0, uint32_t b1) {
    asm volatile(
        "mma.sync.aligned.m16n8k16.row.col.f32.f16.f16.f32 "
        "{%0,%1,%2,%3}, {%4,%5,%6,%7}, {%8,%9}, {%0,%1,%2,%3};"
        : "+f"(c[0]), "+f"(c[1]), "+f"(c[2]), "+f"(c[3])
        : "r"(a[0]), "r"(a[1]), "r"(a[2]), "r"(a[3]), "r"(b0), "r"(b1));
}

// D += A*B : m16n8k16 fp16 inputs, fp16 accum (2 half2 regs)
__device__ __forceinline__ void mma16h(uint32_t c[2], const uint32_t a[4], uint32_t b0, uint32_t b1) {
    asm volatile(
        "mma.sync.aligned.m16n8k16.row.col.f16.f16.f16.f16 "
        "{%0,%1}, {%2,%3,%4,%5}, {%6,%7}, {%0,%1};"
        : "+r"(c[0]), "+r"(c[1])
        : "r"(a[0]), "r"(a[1]), "r"(a[2]), "r"(a[3]), "r"(b0), "r"(b1));
}

__device__ __forceinline__ void ldsm4(uint32_t r[4], uint32_t a) {
    asm volatile("ldmatrix.sync.aligned.m8n8.x4.shared.b16 {%0,%1,%2,%3}, [%4];"
        : "=r"(r[0]), "=r"(r[1]), "=r"(r[2]), "=r"(r[3]) : "r"(a));
}
__device__ __forceinline__ void ldsm4t(uint32_t r[4], uint32_t a) {
    asm volatile("ldmatrix.sync.aligned.m8n8.x4.trans.shared.b16 {%0,%1,%2,%3}, [%4];"
        : "=r"(r[0]), "=r"(r[1]), "=r"(r[2]), "=r"(r[3]) : "r"(a));
}

__device__ __forceinline__ uint32_t f2h2(float a, float b) {
    __half2 h = __floats2half2_rn(a, b);
    return *(uint32_t*)&h;
}
__device__ __forceinline__ uint32_t smem32(const void* p) {
    return (uint32_t)__cvta_generic_to_shared(p);
}
__device__ __forceinline__ float ex2f(float x) {
    float y; asm("ex2.approx.ftz.f32 %0, %1;" : "=f"(y) : "f"(x)); return y;
}
__device__ __forceinline__ float lg2f(float x) {
    float y; asm("lg2.approx.ftz.f32 %0, %1;" : "=f"(y) : "f"(x)); return y;
}
// P' = log2(1 + 2^x)  (softplus with scales folded into k and v)
__device__ __forceinline__ float softplus2_f(float x) {
    return lg2f(1.f + ex2f(x));
}

// ---------------------------------------------------------------------------
// W transpose + fp16 round:  g_Wh[p][n][k] = half(W[p][k][n])
// ---------------------------------------------------------------------------
__global__ __launch_bounds__(256) void wt_kernel(
    const float* __restrict__ Wk, const float* __restrict__ Wq, const float* __restrict__ Wv)
{
    __shared__ float t[64][17];
    const float* __restrict__ W = (blockIdx.y == 0) ? Wk : ((blockIdx.y == 1) ? Wq : Wv);
    const int k0 = blockIdx.x * 16;
    const int tid = threadIdx.x;
    #pragma unroll
    for (int i = 0; i < 4; ++i) {
        int idx = i * 256 + tid;
        int kk = idx >> 6, n = idx & 63;
        t[n][kk] = W[(size_t)(k0 + kk) * HEAD + n];
    }
    __syncthreads();
    #pragma unroll
    for (int i = 0; i < 4; ++i) {
        int idx = i * 256 + tid;
        int n = idx >> 4, kk = idx & 15;
        g_Wh[blockIdx.y][n][k0 + kk] = __float2half_rn(t[n][kk]);
    }
}

// ---------------------------------------------------------------------------
// Projection via fp16 mma + ldmatrix. CTA: 128(m) x 192(n), K chunk 32,
// ping-pong buffers, 1 barrier/chunk. Row stride 40 halves (80 B).
// Epilogue folds softplus constants: k *= log2e/32, v *= ln2.
// ---------------------------------------------------------------------------
#define PST 40
#define PSTB 80
#define PROJ_X_H   (128 * PST)
#define PROJ_W_H   (192 * PST)
#define PROJ_SMEM  ((2 * PROJ_X_H + 2 * PROJ_W_H) * 2)   // 51200 B

__global__ __launch_bounds__(256, 1) void proj_mma_kernel(
    const float* __restrict__ x,
    const float* __restrict__ bk, const float* __restrict__ bq, const float* __restrict__ bv)
{
    extern __shared__ __half psm[];
    __half* xsb = psm;
    __half* wsb = psm + 2 * PROJ_X_H;

    const int tid  = threadIdx.x;
    const int wid  = tid >> 5, lane = tid & 31;
    const int wm   = wid >> 1, wn = wid & 1;
    const int g    = lane >> 2, t = lane & 3;
    const int m0   = blockIdx.x * 128;
    const int lm   = lane >> 3, lrr = lane & 7;

    const uint32_t psm32 = smem32(psm);
    const uint32_t xs32[2] = { psm32, psm32 + PROJ_X_H * 2 };
    const uint32_t ws32[2] = { psm32 + 4 * PROJ_X_H, psm32 + 4 * PROJ_X_H + PROJ_W_H * 2 };

    const uint32_t paoff = (uint32_t)((wm * 32 + (lm & 1) * 8 + lrr) * PSTB + (lm >> 1) * 16);
    const uint32_t pboff = (uint32_t)((wn * 96 + (lm >> 1) * 8 + lrr) * PSTB + (lm & 1) * 16);

    int xrow[4], xcol[4], wrow[3], wcol[3];
    #pragma unroll
    for (int i = 0; i < 4; ++i) { int idx = i * 256 + tid; xrow[i] = idx >> 3; xcol[i] = (idx & 7) * 4; }
    #pragma unroll
    for (int i = 0; i < 3; ++i) { int idx = i * 256 + tid; wrow[i] = idx >> 2; wcol[i] = (idx & 3) * 8; }

    float c[2][12][4];
    #pragma unroll
    for (int mt = 0; mt < 2; ++mt)
        #pragma unroll
        for (int nt = 0; nt < 12; ++nt)
            #pragma unroll
            for (int r = 0; r < 4; ++r) c[mt][nt][r] = 0.f;

    uint2 xr[4];
    uint4 wr[3];

    #pragma unroll
    for (int i = 0; i < 4; ++i) {
        float4 v = *(const float4*)&x[(size_t)(m0 + xrow[i]) * NEMB + xcol[i]];
        xr[i].x = f2h2(v.x, v.y); xr[i].y = f2h2(v.z, v.w);
    }
    #pragma unroll
    for (int i = 0; i < 3; ++i)
        wr[i] = *(const uint4*)&g_Wh[wrow[i] >> 6][wrow[i] & 63][wcol[i]];
    #pragma unroll
    for (int i = 0; i < 4; ++i)
        *(uint2*)&xsb[xrow[i] * PST + xcol[i]] = xr[i];
    #pragma unroll
    for (int i = 0; i < 3; ++i)
        *(uint4*)&wsb[wrow[i] * PST + wcol[i]] = wr[i];
    __syncthreads();

    for (int ch = 0; ch < 32; ++ch) {
        const int cur = ch & 1;
        __half* xsn = xsb + (cur ^ 1) * PROJ_X_H;
        __half* wsn = wsb + (cur ^ 1) * PROJ_W_H;

        if (ch < 31) {
            const int k1 = (ch + 1) * 32;
            #pragma unroll
            for (int i = 0; i < 4; ++i) {
                float4 v = *(const float4*)&x[(size_t)(m0 + xrow[i]) * NEMB + k1 + xcol[i]];
                xr[i].x = f2h2(v.x, v.y); xr[i].y = f2h2(v.z, v.w);
            }
            #pragma unroll
            for (int i = 0; i < 3; ++i)
                wr[i] = *(const uint4*)&g_Wh[wrow[i] >> 6][wrow[i] & 63][k1 + wcol[i]];
        }

        uint32_t A[2][2][4];
        #pragma unroll
        for (int mt = 0; mt < 2; ++mt)
            #pragma unroll
            for (int kt = 0; kt < 2; ++kt)
                ldsm4(A[mt][kt], xs32[cur] + paoff + (uint32_t)(mt * 16 * PSTB + kt * 32));

        #pragma unroll
        for (int kt = 0; kt < 2; ++kt) {
            #pragma unroll
            for (int p2 = 0; p2 < 6; ++p2) {
                uint32_t B4[4];
                ldsm4(B4, ws32[cur] + pboff + (uint32_t)(p2 * 16 * PSTB + kt * 32));
                mma16(c[0][2 * p2    ], A[0][kt], B4[0], B4[1]);
                mma16(c[0][2 * p2 + 1], A[0][kt], B4[2], B4[3]);
                mma16(c[1][2 * p2    ], A[1][kt], B4[0], B4[1]);
                mma16(c[1][2 * p2 + 1], A[1][kt], B4[2], B4[3]);
            }
        }

        if (ch < 31) {
            #pragma unroll
            for (int i = 0; i < 4; ++i)
                *(uint2*)&xsn[xrow[i] * PST + xcol[i]] = xr[i];
            #pragma unroll
            for (int i = 0; i < 3; ++i)
                *(uint4*)&wsn[wrow[i] * PST + wcol[i]] = wr[i];
        }
        __syncthreads();
    }

    // epilogue: fp32 bias add, constant folding, fp16 store
    // k (p=0): *log2e/32 ; q (p=1): *1 ; v (p=2): *ln2
    const float* biases[3] = {bk, bq, bv};
    const float scales[3] = {0.04511294f, 1.f, 0.69314718f};
    #pragma unroll
    for (int nt = 0; nt < 12; ++nt) {
        const int ng0 = wn * 96 + nt * 8;
        const int p = ng0 >> 6;
        const int n = (ng0 & 63) + 2 * t;
        const float* __restrict__ bias = biases[p];
        const float sc = scales[p];
        const float b0 = bias[n], b1 = bias[n + 1];
        #pragma unroll
        for (int mt = 0; mt < 2; ++mt) {
            const int row = m0 + wm * 32 + mt * 16 + g;
            *(uint32_t*)&g_kqv[p][row    ][n] = f2h2((c[mt][nt][0] + b0) * sc, (c[mt][nt][1] + b1) * sc);
            *(uint32_t*)&g_kqv[p][row + 8][n] = f2h2((c[mt][nt][2] + b0) * sc, (c[mt][nt][3] + b1) * sc);
        }
    }
}

// ---------------------------------------------------------------------------
// Attention: P-in-registers + paired s-blocks + ldmatrix + f16-accum S-phase.
// P' = log2(1 + 2^x) (scales folded into k and v at projection time).
// ---------------------------------------------------------------------------
#define ASTH 72
#define ASTB 144
#define TILE_H (64 * ASTH)
#define ATTN_SMEM (9 * TILE_H * 2)          // ks + 4*qs + 4*vs = 82944 B

__global__ __launch_bounds__(256, 1) void attn_kernel(float* __restrict__ out)
{
    extern __shared__ __half smh[];
    __half* ks  = smh;                       // [64][ASTH]  K tile [t][h]
    __half* qsb = smh + TILE_H;              // 4 x Q tiles [s][h]
    __half* vsb = smh + 5 * TILE_H;          // 4 x V tiles [s][h] (natural)
    float*  stage = (float*)qsb;             // epilogue staging (reused)

    const int b    = blockIdx.y;
    const int tid  = threadIdx.x;
    const int wid  = tid >> 5, lane = tid & 31;
    const int wm   = wid >> 1, wn = wid & 1;
    const int g    = lane >> 2, t = lane & 3;
    const int lm   = lane >> 3, lrr = lane & 7;
    const int trow = wm * 16 + g;

    const uint32_t sm32 = smem32(smh);
    const uint32_t ks32 = sm32;
    uint32_t qs32[4], vs32[4];
    #pragma unroll
    for (int s = 0; s < 4; ++s) {
        qs32[s] = sm32 + (uint32_t)((1 + s) * TILE_H * 2);
        vs32[s] = sm32 + (uint32_t)((5 + s) * TILE_H * 2);
    }

    const uint32_t kaoff = (uint32_t)((wm * 16 + (lm & 1) * 8 + lrr) * ASTB + (lm >> 1) * 16);
    const uint32_t qboff = (uint32_t)((wn * 32 + (lm >> 1) * 8 + lrr) * ASTB + (lm & 1) * 16);
    const uint32_t vboff = (uint32_t)(((lm & 1) * 8 + lrr) * ASTB + (lm >> 1) * 16);

    int qrow[4], qcol[4];
    #pragma unroll
    for (int i = 0; i < 4; ++i) { int idx = i * 256 + tid; qrow[i] = idx >> 4; qcol[i] = (idx & 15) * 4; }

    const __half* __restrict__ Kg = &g_kqv[0][(size_t)b * SEQ][0];
    const __half* __restrict__ Qg = &g_kqv[1][(size_t)b * SEQ][0];
    const __half* __restrict__ Vg = &g_kqv[2][(size_t)b * SEQ][0];

    for (int hf = 0; hf < 2; ++hf) {
        const int tb = hf ? (NTB - 1 - (int)blockIdx.x) : (int)blockIdx.x;
        const int nblocks = tb + 1;
        const int npairs  = nblocks >> 1;

        // K tile [t][h]
        #pragma unroll
        for (int i = 0; i < 4; ++i) {
            uint2 u = *(const uint2*)&Kg[(size_t)(tb * 64 + qrow[i]) * HEAD + qcol[i]];
            *(uint2*)&ks[qrow[i] * ASTH + qcol[i]] = u;
        }

        // prologue: blocks 0 (and 1) into slots 0,1
        #pragma unroll
        for (int blk = 0; blk < 2; ++blk) {
            if (blk > tb) break;
            __half* qs = qsb + blk * TILE_H;
            __half* vs = vsb + blk * TILE_H;
            const size_t s0 = (size_t)blk * 64;
            #pragma unroll
            for (int i = 0; i < 4; ++i) {
                *(uint2*)&qs[qrow[i] * ASTH + qcol[i]] =
                    *(const uint2*)&Qg[(s0 + qrow[i]) * HEAD + qcol[i]];
                *(uint2*)&vs[qrow[i] * ASTH + qcol[i]] =
                    *(const uint2*)&Vg[(s0 + qrow[i]) * HEAD + qcol[i]];
            }
        }
        __syncthreads();

        // K A-fragments via ldmatrix, resident across the s-loop
        uint32_t A[4][4];
        #pragma unroll
        for (int kt = 0; kt < 4; ++kt)
            ldsm4(A[kt], ks32 + kaoff + (uint32_t)(kt * 32));

        float o[8][4];
        #pragma unroll
        for (int nt = 0; nt < 8; ++nt)
            #pragma unroll
            for (int r = 0; r < 4; ++r) o[nt][r] = 0.f;

        uint2 qrh[2][4], vrh[2][4];

        for (int p = 0; p < npairs; ++p) {
            const int base  = (p & 1) * 2;
            const int nbase = ((p + 1) & 1) * 2;
            const int b1 = 2 * p + 1;

            const int pf0 = 2 * p + 2, pf1 = 2 * p + 3;
            const bool v0 = pf0 <= tb, v1 = pf1 <= tb;
            if (v0) {
                const size_t s1 = (size_t)pf0 * 64;
                #pragma unroll
                for (int i = 0; i < 4; ++i) {
                    qrh[0][i] = *(const uint2*)&Qg[(s1 + qrow[i]) * HEAD + qcol[i]];
                    vrh[0][i] = *(const uint2*)&Vg[(s1 + qrow[i]) * HEAD + qcol[i]];
                }
            }
            if (v1) {
                const size_t s1 = (size_t)pf1 * 64;
                #pragma unroll
                for (int i = 0; i < 4; ++i) {
                    qrh[1][i] = *(const uint2*)&Qg[(s1 + qrow[i]) * HEAD + qcol[i]];
                    vrh[1][i] = *(const uint2*)&Vg[(s1 + qrow[i]) * HEAD + qcol[i]];
                }
            }

            // S-phase for both blocks, fp16 accumulators
            uint32_t s_c[2][4][2];
            #pragma unroll
            for (int blk = 0; blk < 2; ++blk)
                #pragma unroll
                for (int nt = 0; nt < 4; ++nt)
                    s_c[blk][nt][0] = s_c[blk][nt][1] = 0u;
            #pragma unroll
            for (int blk = 0; blk < 2; ++blk) {
                const uint32_t qb = qs32[base + blk];
                #pragma unroll
                for (int kt = 0; kt < 4; ++kt) {
                    #pragma unroll
                    for (int p2 = 0; p2 < 2; ++p2) {
                        uint32_t B4[4];
                        ldsm4(B4, qb + qboff + (uint32_t)(p2 * 16 * ASTB + kt * 32));
                        mma16h(s_c[blk][2 * p2    ], A[kt], B4[0], B4[1]);
                        mma16h(s_c[blk][2 * p2 + 1], A[kt], B4[2], B4[3]);
                    }
                }
            }

            // softplus2 both blocks; diag only possible on blk 1
            uint32_t pa[2][2][4];
            #pragma unroll
            for (int blk = 0; blk < 2; ++blk) {
                const bool diag = (blk == 1) && (b1 == tb);
                #pragma unroll
                for (int nt = 0; nt < 4; ++nt) {
                    const int sc = wn * 32 + nt * 8 + 2 * t;
                    float2 lo = __half22float2(*(__half2*)&s_c[blk][nt][0]);
                    float2 hi = __half22float2(*(__half2*)&s_c[blk][nt][1]);
                    float p0 = softplus2_f(lo.x);
                    float p1 = softplus2_f(lo.y);
                    float p2 = softplus2_f(hi.x);
                    float p3 = softplus2_f(hi.y);
                    if (diag) {
                        if (sc     > trow    ) p0 = 0.f;
                        if (sc + 1 > trow    ) p1 = 0.f;
                        if (sc     > trow + 8) p2 = 0.f;
                        if (sc + 1 > trow + 8) p3 = 0.f;
                    }
                    const int j = nt >> 1;
                    if ((nt & 1) == 0) { pa[blk][j][0] = f2h2(p0, p1); pa[blk][j][1] = f2h2(p2, p3); }
                    else               { pa[blk][j][2] = f2h2(p0, p1); pa[blk][j][3] = f2h2(p2, p3); }
                }
            }

            // O-phase for both blocks (fp32 accum; B via ldmatrix.trans)
            #pragma unroll
            for (int blk = 0; blk < 2; ++blk) {
                const uint32_t vb = vs32[base + blk];
                #pragma unroll
                for (int j = 0; j < 2; ++j) {
                    const uint32_t vjb = vb + (uint32_t)((wn * 32 + j * 16) * ASTB) + vboff;
                    #pragma unroll
                    for (int q = 0; q < 4; ++q) {
                        uint32_t B4[4];
                        ldsm4t(B4, vjb + (uint32_t)(q * 32));
                        mma16(o[2 * q    ], pa[blk][j], B4[0], B4[1]);
                        mma16(o[2 * q + 1], pa[blk][j], B4[2], B4[3]);
                    }
                }
            }

            if (v0) {
                __half* qsn = qsb + nbase * TILE_H;
                __half* vsn = vsb + nbase * TILE_H;
                #pragma unroll
                for (int i = 0; i < 4; ++i) {
                    *(uint2*)&qsn[qrow[i] * ASTH + qcol[i]] = qrh[0][i];
                    *(uint2*)&vsn[qrow[i] * ASTH + qcol[i]] = vrh[0][i];
                }
            }
            if (v1) {
                __half* qsn = qsb + (nbase + 1) * TILE_H;
                __half* vsn = vsb + (nbase + 1) * TILE_H;
                #pragma unroll
                for (int i = 0; i < 4; ++i) {
                    *(uint2*)&qsn[qrow[i] * ASTH + qcol[i]] = qrh[1][i];
                    *(uint2*)&vsn[qrow[i] * ASTH + qcol[i]] = vrh[1][i];
                }
            }
            __syncthreads();
        }

        // peeled odd block (always the diagonal, sb = tb)
        if (nblocks & 1) {
            const int base = (npairs & 1) * 2;
            const uint32_t qb = qs32[base];
            const uint32_t vb = vs32[base];

            uint32_t s_c[4][2];
            #pragma unroll
            for (int nt = 0; nt < 4; ++nt) s_c[nt][0] = s_c[nt][1] = 0u;
            #pragma unroll
            for (int kt = 0; kt < 4; ++kt) {
                #pragma unroll
                for (int p2 = 0; p2 < 2; ++p2) {
                    uint32_t B4[4];
                    ldsm4(B4, qb + qboff + (uint32_t)(p2 * 16 * ASTB + kt * 32));
                    mma16h(s_c[2 * p2    ], A[kt], B4[0], B4[1]);
                    mma16h(s_c[2 * p2 + 1], A[kt], B4[2], B4[3]);
                }
            }

            uint32_t pa[2][4];
            #pragma unroll
            for (int nt = 0; nt < 4; ++nt) {
                const int sc = wn * 32 + nt * 8 + 2 * t;
                float2 lo = __half22float2(*(__half2*)&s_c[nt][0]);
                float2 hi = __half22float2(*(__half2*)&s_c[nt][1]);
                float p0 = softplus2_f(lo.x);
                float p1 = softplus2_f(lo.y);
                float p2 = softplus2_f(hi.x);
                float p3 = softplus2_f(hi.y);
                if (sc     > trow    ) p0 = 0.f;
                if (sc + 1 > trow    ) p1 = 0.f;
                if (sc     > trow + 8) p2 = 0.f;
                if (sc + 1 > trow + 8) p3 = 0.f;
                const int j = nt >> 1;
                if ((nt & 1) == 0) { pa[j][0] = f2h2(p0, p1); pa[j][1] = f2h2(p2, p3); }
                else               { pa[j][2] = f2h2(p0, p1); pa[j][3] = f2h2(p2, p3); }
            }

            #pragma unroll
            for (int j = 0; j < 2; ++j) {
                const uint32_t vjb = vb + (uint32_t)((wn * 32 + j * 16) * ASTB) + vboff;
                #pragma unroll
                for (int q = 0; q < 4; ++q) {
                    uint32_t B4[4];
                    ldsm4t(B4, vjb + (uint32_t)(q * 32));
                    mma16(o[2 * q    ], pa[j], B4[0], B4[1]);
                    mma16(o[2 * q + 1], pa[j], B4[2], B4[3]);
                }
            }
            __syncthreads();
        }

        // cross-wn reduction (once per t-block): wn=1 stages, wn=0 adds+writes
        if (wn == 1) {
            #pragma unroll
            for (int nt = 0; nt < 8; ++nt) {
                const int col = nt * 8 + 2 * t;
                *(float2*)&stage[(wm * 16 + g    ) * 64 + col] = make_float2(o[nt][0], o[nt][1]);
                *(float2*)&stage[(wm * 16 + g + 8) * 64 + col] = make_float2(o[nt][2], o[nt][3]);
            }
        }
        __syncthreads();
        if (wn == 0) {
            const size_t row0 = (size_t)b * SEQ + tb * 64 + trow;
            #pragma unroll
            for (int nt = 0; nt < 8; ++nt) {
                const int col = nt * 8 + 2 * t;
                float2 s0 = *(const float2*)&stage[(wm * 16 + g    ) * 64 + col];
                float2 s1 = *(const float2*)&stage[(wm * 16 + g + 8) * 64 + col];
                *(float2*)&out[(row0    ) * HEAD + col] = make_float2(o[nt][0] + s0.x, o[nt][1] + s0.y);
                *(float2*)&out[(row0 + 8) * HEAD + col] = make_float2(o[nt][2] + s1.x, o[nt][3] + s1.y);
            }
        }
        __syncthreads();
    }
}

// ---------------------------------------------------------------------------
extern "C" void kernel_launch(void* const* d_in, const int* in_sizes, int n_in,
                              void* d_out, int out_size)
{
    const float* x  = (const float*)d_in[0];
    const float* Wk = (const float*)d_in[1];
    const float* bk = (const float*)d_in[2];
    const float* Wq = (const float*)d_in[3];
    const float* bq = (const float*)d_in[4];
    const float* Wv = (const float*)d_in[5];
    const float* bv = (const float*)d_in[6];
    float* out = (float*)d_out;

    static int init = 0;
    if (!init) {
        cudaFuncSetAttribute(attn_kernel, cudaFuncAttributeMaxDynamicSharedMemorySize, ATTN_SMEM);
        cudaFuncSetAttribute(proj_mma_kernel, cudaFuncAttributeMaxDynamicSharedMemorySize, PROJ_SMEM);
        init = 1;
    }

    dim3 wg(NEMB / 16, 3);
    wt_kernel<<<wg, 256>>>(Wk, Wq, Wv);

    proj_mma_kernel<<<MTOT / 128, 256, PROJ_SMEM>>>(x, bk, bq, bv);

    dim3 ag(NTB / 2, BATCH);
    attn_kernel<<<ag, 256, ATTN_SMEM>>>(out);
}